// round 1
// baseline (speedup 1.0000x reference)
#include <cuda_runtime.h>
#include <math.h>

#define SQ 4096
#define DM 1024
#define NH 16
#define DH 64

// Scratch (static device globals — no allocations allowed)
__device__ float g_Qp[NH * SQ * DH];   // [H][S][DH]
__device__ float g_Kp[NH * SQ * DH];
__device__ float g_Vp[NH * SQ * DH];
__device__ float g_O [SQ * DM];        // concat layout [S][H*DH]

// ---------------------------------------------------------------------------
// Per-head projection: out[h][s][e] = sum_d X[s][d] * W[h][d][e] + b[h][e]
// One block computes a 64(row) x 64(=DH) tile for one head. BK=16, 4x4 regs.
// ---------------------------------------------------------------------------
__global__ __launch_bounds__(256) void proj_kernel(
    const float* __restrict__ X, const float* __restrict__ W,
    const float* __restrict__ b, float* __restrict__ out)
{
    const int h  = blockIdx.y;
    const int s0 = blockIdx.x * 64;
    __shared__ float Xs[16][68];   // [k][m]  (padded)
    __shared__ float Ws[16][68];   // [k][n]
    const int tid = threadIdx.x;
    const int tr = tid >> 4, tc = tid & 15;
    float acc[4][4] = {};
    const float* Wh = W + h * DM * DH;

    for (int kk = 0; kk < DM; kk += 16) {
        #pragma unroll
        for (int i = 0; i < 4; i++) {
            int idx = tid + i * 256;                 // 1024 elems each
            Xs[idx & 15][idx >> 4] = X[(s0 + (idx >> 4)) * DM + kk + (idx & 15)];
            Ws[idx >> 6][idx & 63] = Wh[(kk + (idx >> 6)) * DH + (idx & 63)];
        }
        __syncthreads();
        #pragma unroll
        for (int k = 0; k < 16; k++) {
            float xv[4], wv[4];
            #pragma unroll
            for (int a = 0; a < 4; a++)  xv[a] = Xs[k][tr * 4 + a];
            #pragma unroll
            for (int bb = 0; bb < 4; bb++) wv[bb] = Ws[k][tc * 4 + bb];
            #pragma unroll
            for (int a = 0; a < 4; a++)
                #pragma unroll
                for (int bb = 0; bb < 4; bb++)
                    acc[a][bb] = fmaf(xv[a], wv[bb], acc[a][bb]);
        }
        __syncthreads();
    }
    #pragma unroll
    for (int a = 0; a < 4; a++)
        #pragma unroll
        for (int bb = 0; bb < 4; bb++) {
            int col = tc * 4 + bb;
            out[h * SQ * DH + (s0 + tr * 4 + a) * DH + col] = acc[a][bb] + b[h * DH + col];
        }
}

// ---------------------------------------------------------------------------
// Flash attention: one block per (head, 64-query tile).
// 256 threads = 16 row-groups x 16 col-groups, each owns a 4x4 score tile.
// Online softmax; P staged via smem for the AV product. Writes concat layout.
// ---------------------------------------------------------------------------
extern __shared__ float fsmem[];

__global__ __launch_bounds__(256) void flash_kernel(
    const float* __restrict__ Qp, const float* __restrict__ Kp,
    const float* __restrict__ Vp, float* __restrict__ Obuf)
{
    const int h  = blockIdx.y;
    const int q0 = blockIdx.x * 64;
    float* Qs = fsmem;               // 64 x 65
    float* Ks = Qs + 64 * 65;
    float* Vs = Ks + 64 * 65;
    float* Ps = Vs + 64 * 65;
    const int tid = threadIdx.x;
    const int rg = tid >> 4, cg = tid & 15;
    const float* Qh = Qp + h * SQ * DH;
    const float* Kh = Kp + h * SQ * DH;
    const float* Vh = Vp + h * SQ * DH;

    #pragma unroll
    for (int i = 0; i < 16; i++) {
        int idx = tid + i * 256;
        Qs[(idx >> 6) * 65 + (idx & 63)] = Qh[(q0 + (idx >> 6)) * DH + (idx & 63)];
    }

    float o[4][4] = {};
    float m[4], l[4];
    #pragma unroll
    for (int a = 0; a < 4; a++) { m[a] = -INFINITY; l[a] = 0.f; }

    const float scl = 0.03125f;   // 1/sqrt(1024)

    for (int kt = 0; kt < SQ / 64; kt++) {
        __syncthreads();          // previous Ps reads done, K/V free to overwrite
        const int k0 = kt * 64;
        #pragma unroll
        for (int i = 0; i < 16; i++) {
            int idx = tid + i * 256;
            int r = idx >> 6, e = idx & 63;
            Ks[r * 65 + e] = Kh[(k0 + r) * DH + e];
            Vs[r * 65 + e] = Vh[(k0 + r) * DH + e];
        }
        __syncthreads();

        float s[4][4] = {};
        #pragma unroll 8
        for (int e = 0; e < 64; e++) {
            float qv[4], kv[4];
            #pragma unroll
            for (int a = 0; a < 4; a++)  qv[a] = Qs[(rg * 4 + a) * 65 + e];
            #pragma unroll
            for (int bb = 0; bb < 4; bb++) kv[bb] = Ks[(cg * 4 + bb) * 65 + e];
            #pragma unroll
            for (int a = 0; a < 4; a++)
                #pragma unroll
                for (int bb = 0; bb < 4; bb++)
                    s[a][bb] = fmaf(qv[a], kv[bb], s[a][bb]);
        }

        #pragma unroll
        for (int a = 0; a < 4; a++) {
            #pragma unroll
            for (int bb = 0; bb < 4; bb++) s[a][bb] *= scl;
            float mloc = fmaxf(fmaxf(s[a][0], s[a][1]), fmaxf(s[a][2], s[a][3]));
            // reduce over the 16 col-groups (aligned 16-lane subgroup of warp)
            #pragma unroll
            for (int mask = 8; mask >= 1; mask >>= 1)
                mloc = fmaxf(mloc, __shfl_xor_sync(0xffffffffu, mloc, mask));
            float mnew  = fmaxf(m[a], mloc);
            float alpha = __expf(m[a] - mnew);    // expf(-inf)=0 on first tile
            float ls = 0.f;
            #pragma unroll
            for (int bb = 0; bb < 4; bb++) {
                s[a][bb] = __expf(s[a][bb] - mnew);
                ls += s[a][bb];
            }
            #pragma unroll
            for (int mask = 8; mask >= 1; mask >>= 1)
                ls += __shfl_xor_sync(0xffffffffu, ls, mask);
            l[a] = l[a] * alpha + ls;
            m[a] = mnew;
            #pragma unroll
            for (int bb = 0; bb < 4; bb++) {
                o[a][bb] *= alpha;
                Ps[(rg * 4 + a) * 65 + cg * 4 + bb] = s[a][bb];
            }
        }
        __syncthreads();

        #pragma unroll 8
        for (int kc = 0; kc < 64; kc++) {
            float pv[4], vv[4];
            #pragma unroll
            for (int a = 0; a < 4; a++)  pv[a] = Ps[(rg * 4 + a) * 65 + kc];
            #pragma unroll
            for (int bb = 0; bb < 4; bb++) vv[bb] = Vs[kc * 65 + cg * 4 + bb];
            #pragma unroll
            for (int a = 0; a < 4; a++)
                #pragma unroll
                for (int bb = 0; bb < 4; bb++)
                    o[a][bb] = fmaf(pv[a], vv[bb], o[a][bb]);
        }
    }

    #pragma unroll
    for (int a = 0; a < 4; a++) {
        float inv = 1.0f / l[a];
        #pragma unroll
        for (int bb = 0; bb < 4; bb++)
            Obuf[(q0 + rg * 4 + a) * DM + h * DH + cg * 4 + bb] = o[a][bb] * inv;
    }
}

// ---------------------------------------------------------------------------
// Output projection: out[s][n] = sum_d X[s][d] * Wo[d][n] + bo[n]
// ---------------------------------------------------------------------------
__global__ __launch_bounds__(256) void outproj_kernel(
    const float* __restrict__ X, const float* __restrict__ W,
    const float* __restrict__ b, float* __restrict__ out)
{
    const int n0 = blockIdx.y * 64;
    const int s0 = blockIdx.x * 64;
    __shared__ float Xs[16][68];
    __shared__ float Ws[16][68];
    const int tid = threadIdx.x;
    const int tr = tid >> 4, tc = tid & 15;
    float acc[4][4] = {};

    for (int kk = 0; kk < DM; kk += 16) {
        #pragma unroll
        for (int i = 0; i < 4; i++) {
            int idx = tid + i * 256;
            Xs[idx & 15][idx >> 4] = X[(s0 + (idx >> 4)) * DM + kk + (idx & 15)];
            Ws[idx >> 6][idx & 63] = W[(kk + (idx >> 6)) * DM + n0 + (idx & 63)];
        }
        __syncthreads();
        #pragma unroll
        for (int k = 0; k < 16; k++) {
            float xv[4], wv[4];
            #pragma unroll
            for (int a = 0; a < 4; a++)  xv[a] = Xs[k][tr * 4 + a];
            #pragma unroll
            for (int bb = 0; bb < 4; bb++) wv[bb] = Ws[k][tc * 4 + bb];
            #pragma unroll
            for (int a = 0; a < 4; a++)
                #pragma unroll
                for (int bb = 0; bb < 4; bb++)
                    acc[a][bb] = fmaf(xv[a], wv[bb], acc[a][bb]);
        }
        __syncthreads();
    }
    #pragma unroll
    for (int a = 0; a < 4; a++)
        #pragma unroll
        for (int bb = 0; bb < 4; bb++) {
            int col = n0 + tc * 4 + bb;
            out[(s0 + tr * 4 + a) * DM + col] = acc[a][bb] + b[col];
        }
}

// ---------------------------------------------------------------------------
extern "C" void kernel_launch(void* const* d_in, const int* in_sizes, int n_in,
                              void* d_out, int out_size) {
    const float* q  = (const float*)d_in[0];
    const float* k  = (const float*)d_in[1];
    const float* v  = (const float*)d_in[2];
    const float* Wq = (const float*)d_in[3];
    const float* bq = (const float*)d_in[4];
    const float* Wk = (const float*)d_in[5];
    const float* bk = (const float*)d_in[6];
    const float* Wv = (const float*)d_in[7];
    const float* bv = (const float*)d_in[8];
    const float* Wo = (const float*)d_in[9];
    const float* bo = (const float*)d_in[10];
    float* out = (float*)d_out;

    void *pQ, *pK, *pV, *pO;
    cudaGetSymbolAddress(&pQ, g_Qp);
    cudaGetSymbolAddress(&pK, g_Kp);
    cudaGetSymbolAddress(&pV, g_Vp);
    cudaGetSymbolAddress(&pO, g_O);
    float* Qp = (float*)pQ;
    float* Kp = (float*)pK;
    float* Vp = (float*)pV;
    float* Ob = (float*)pO;

    const int flash_smem = 4 * 64 * 65 * (int)sizeof(float);   // 66560 B
    cudaFuncSetAttribute(flash_kernel, cudaFuncAttributeMaxDynamicSharedMemorySize,
                         flash_smem);

    dim3 blk(256);
    dim3 gproj(SQ / 64, NH);
    proj_kernel<<<gproj, blk>>>(q, Wq, bq, Qp);
    proj_kernel<<<gproj, blk>>>(k, Wk, bk, Kp);
    proj_kernel<<<gproj, blk>>>(v, Wv, bv, Vp);

    dim3 gflash(SQ / 64, NH);
    flash_kernel<<<gflash, blk, flash_smem>>>(Qp, Kp, Vp, Ob);

    dim3 gout(SQ / 64, DM / 64);
    outproj_kernel<<<gout, blk>>>(Ob, Wo, bo, out);
}

// round 2
// speedup vs baseline: 5.0483x; 5.0483x over previous
#include <cuda_runtime.h>
#include <math.h>

#define SQ 4096
#define DM 1024
#define NH 16
#define DH 64

// Scratch (static device globals — no allocations allowed). Concat layout [S][DM].
__device__ float g_Qc[SQ * DM];
__device__ float g_Kc[SQ * DM];
__device__ float g_Vc[SQ * DM];
__device__ float g_Oc[SQ * DM];

// ---------------------------------------------------------------------------
// helpers
// ---------------------------------------------------------------------------
__device__ __forceinline__ unsigned f2tf(float f) {
    unsigned r;
    asm("cvt.rna.tf32.f32 %0, %1;" : "=r"(r) : "f"(f));
    return r;
}

__device__ __forceinline__ void mma8(float c[4], const unsigned a[4], const unsigned b[2]) {
    asm volatile(
        "mma.sync.aligned.m16n8k8.row.col.f32.tf32.tf32.f32 "
        "{%0,%1,%2,%3}, {%4,%5,%6,%7}, {%8,%9}, {%0,%1,%2,%3};"
        : "+f"(c[0]), "+f"(c[1]), "+f"(c[2]), "+f"(c[3])
        : "r"(a[0]), "r"(a[1]), "r"(a[2]), "r"(a[3]), "r"(b[0]), "r"(b[1]));
}

// ---------------------------------------------------------------------------
// TF32 GEMM: out[m][n] = sum_k X[m][k] * W(k,n) + bias[n]
// headed=1: W(k,n) = W[(n>>6)*DM*DH + k*DH + (n&63)]   (per-head [H][D][DH])
// headed=0: W(k,n) = W[k*DM + n]                       (plain [D][D])
// Block: 256 thr (8 warps, 2x4 warp grid), tile 128x128, BK=32.
// ---------------------------------------------------------------------------
__global__ __launch_bounds__(256, 2) void gemm_tf32(
    const float* __restrict__ X, const float* __restrict__ W,
    const float* __restrict__ bias, float* __restrict__ out, int headed)
{
    __shared__ unsigned As[128 * 36];   // [m][k], pitch 36 (≡4 mod 32 → CF frag reads)
    __shared__ unsigned Bs[128 * 36];   // [n][k], pitch 36

    const int t = threadIdx.x, lane = t & 31, w = t >> 5;
    const int wm = w >> 2, wn = w & 3;              // 2 x 4 warps
    const int m0 = blockIdx.x * 128, n0 = blockIdx.y * 128;
    const int qm = lane & 3, gid = lane >> 2;

    float acc[4][4][4] = {};                        // [mt][nt][frag]

    for (int kk = 0; kk < DM; kk += 32) {
        __syncthreads();
        // A tile: 128x32, float4 per thread x4, STS.128 (conflict-free phases)
        #pragma unroll
        for (int i = 0; i < 4; i++) {
            int m = (t >> 3) + i * 32;
            int k = (t & 7) * 4;
            float4 v = *(const float4*)&X[(m0 + m) * DM + kk + k];
            uint4 pv = { f2tf(v.x), f2tf(v.y), f2tf(v.z), f2tf(v.w) };
            *(uint4*)&As[m * 36 + k] = pv;
        }
        // B tile: 32x128 -> transposed to Bs[n][k]; coalesced global, 4-way STS
        #pragma unroll
        for (int j = 0; j < 16; j++) {
            int k = w * 4 + (j >> 2);
            int n = (j & 3) * 32 + lane;
            int ng = n0 + n;
            float v = headed ? W[(ng >> 6) * (DM * DH) + (kk + k) * DH + (ng & 63)]
                             : W[(kk + k) * DM + ng];
            Bs[n * 36 + k] = f2tf(v);
        }
        __syncthreads();

        #pragma unroll
        for (int k8 = 0; k8 < 4; k8++) {
            int kb = k8 * 8 + qm;
            unsigned a[4][4];
            #pragma unroll
            for (int mt = 0; mt < 4; mt++) {
                int m = wm * 64 + mt * 16 + gid;
                a[mt][0] = As[m * 36 + kb];
                a[mt][1] = As[(m + 8) * 36 + kb];
                a[mt][2] = As[m * 36 + kb + 4];
                a[mt][3] = As[(m + 8) * 36 + kb + 4];
            }
            #pragma unroll
            for (int nt = 0; nt < 4; nt++) {
                int n = wn * 32 + nt * 8 + gid;
                unsigned b[2] = { Bs[n * 36 + kb], Bs[n * 36 + kb + 4] };
                #pragma unroll
                for (int mt = 0; mt < 4; mt++) mma8(acc[mt][nt], a[mt], b);
            }
        }
    }

    #pragma unroll
    for (int mt = 0; mt < 4; mt++) {
        int r = m0 + wm * 64 + mt * 16 + gid;
        #pragma unroll
        for (int nt = 0; nt < 4; nt++) {
            int c = n0 + wn * 32 + nt * 8 + 2 * qm;
            float b0 = bias[c], b1 = bias[c + 1];
            out[r * DM + c]           = acc[mt][nt][0] + b0;
            out[r * DM + c + 1]       = acc[mt][nt][1] + b1;
            out[(r + 8) * DM + c]     = acc[mt][nt][2] + b0;
            out[(r + 8) * DM + c + 1] = acc[mt][nt][3] + b1;
        }
    }
}

// ---------------------------------------------------------------------------
// Flash attention, tf32 mma. Block = (head, 128-query tile), 8 warps x 16 rows.
// K-tiles of 64 keys. Q prescaled by 1/32 (= 1/sqrt(1024)).
// P moved C-layout -> A-layout via quad shuffles (no smem round trip).
// ---------------------------------------------------------------------------
extern __shared__ unsigned fsm[];

__global__ __launch_bounds__(256, 2) void flash_tf32(
    const float* __restrict__ Qc, const float* __restrict__ Kc,
    const float* __restrict__ Vc, float* __restrict__ Oc)
{
    unsigned* Qs = fsm;                 // 128 x 68 (pitch ≡4 mod 32)
    unsigned* Ks = Qs + 128 * 68;       // 64 x 68
    unsigned* Vs = Ks + 64 * 68;        // 64 x 68

    const int t = threadIdx.x, lane = t & 31, w = t >> 5;
    const int h = blockIdx.y, q0 = blockIdx.x * 128;
    const int hc = h * DH;
    const int qm = lane & 3, gid = lane >> 2;
    const int s0l = (lane & ~3) | (qm >> 1);    // quad src for cols 0..3
    const int s1l = s0l | 2;                    // quad src for cols 4..7

    // load Q tile (scaled)
    #pragma unroll
    for (int i = 0; i < 8; i++) {
        int idx = t + i * 256;              // 2048 float4s
        int r = idx >> 4, c4 = (idx & 15) * 4;
        float4 v = *(const float4*)&Qc[(q0 + r) * DM + hc + c4];
        uint4 pv = { f2tf(v.x * 0.03125f), f2tf(v.y * 0.03125f),
                     f2tf(v.z * 0.03125f), f2tf(v.w * 0.03125f) };
        *(uint4*)&Qs[r * 68 + c4] = pv;
    }

    float mst[2] = { -INFINITY, -INFINITY };
    float lst[2] = { 0.f, 0.f };
    float accO[8][4] = {};

    for (int kt = 0; kt < SQ / 64; kt++) {
        __syncthreads();                    // prior Vs reads done
        int k0 = kt * 64;
        #pragma unroll
        for (int i = 0; i < 4; i++) {
            int idx = t + i * 256;
            int r = idx >> 4, c4 = (idx & 15) * 4;
            float4 kv = *(const float4*)&Kc[(k0 + r) * DM + hc + c4];
            uint4 pk = { f2tf(kv.x), f2tf(kv.y), f2tf(kv.z), f2tf(kv.w) };
            *(uint4*)&Ks[r * 68 + c4] = pk;
            float4 vv = *(const float4*)&Vc[(k0 + r) * DM + hc + c4];
            uint4 pw = { f2tf(vv.x), f2tf(vv.y), f2tf(vv.z), f2tf(vv.w) };
            *(uint4*)&Vs[r * 68 + c4] = pw;
        }
        __syncthreads();

        // S = Q K^T  (16 rows x 64 keys per warp)
        float sacc[8][4] = {};
        #pragma unroll
        for (int k8 = 0; k8 < 8; k8++) {
            int kb = k8 * 8 + qm;
            int m = w * 16 + gid;
            unsigned a[4] = { Qs[m * 68 + kb], Qs[(m + 8) * 68 + kb],
                              Qs[m * 68 + kb + 4], Qs[(m + 8) * 68 + kb + 4] };
            #pragma unroll
            for (int nt = 0; nt < 8; nt++) {
                int n = nt * 8 + gid;
                unsigned b[2] = { Ks[n * 68 + kb], Ks[n * 68 + kb + 4] };
                mma8(sacc[nt], a, b);
            }
        }

        // online softmax per row-half (rows gid and gid+8 within warp tile)
        #pragma unroll
        for (int rh = 0; rh < 2; rh++) {
            float mx = -INFINITY;
            #pragma unroll
            for (int nt = 0; nt < 8; nt++)
                mx = fmaxf(mx, fmaxf(sacc[nt][rh * 2], sacc[nt][rh * 2 + 1]));
            mx = fmaxf(mx, __shfl_xor_sync(0xffffffffu, mx, 1));
            mx = fmaxf(mx, __shfl_xor_sync(0xffffffffu, mx, 2));
            float mnew = fmaxf(mst[rh], mx);
            float alpha = __expf(mst[rh] - mnew);   // 0 on first tile
            mst[rh] = mnew;
            float ls = 0.f;
            #pragma unroll
            for (int nt = 0; nt < 8; nt++) {
                float p0 = __expf(sacc[nt][rh * 2] - mnew);
                float p1 = __expf(sacc[nt][rh * 2 + 1] - mnew);
                sacc[nt][rh * 2] = p0;
                sacc[nt][rh * 2 + 1] = p1;
                ls += p0 + p1;
            }
            ls += __shfl_xor_sync(0xffffffffu, ls, 1);
            ls += __shfl_xor_sync(0xffffffffu, ls, 2);
            lst[rh] = lst[rh] * alpha + ls;
            #pragma unroll
            for (int et = 0; et < 8; et++) {
                accO[et][rh * 2]     *= alpha;
                accO[et][rh * 2 + 1] *= alpha;
            }
        }

        // O += P V : P C-layout -> A-layout via quad shuffles, then mma
        #pragma unroll
        for (int kt8 = 0; kt8 < 8; kt8++) {
            float v00 = __shfl_sync(0xffffffffu, sacc[kt8][0], s0l);
            float v01 = __shfl_sync(0xffffffffu, sacc[kt8][1], s0l);
            float v10 = __shfl_sync(0xffffffffu, sacc[kt8][2], s0l);
            float v11 = __shfl_sync(0xffffffffu, sacc[kt8][3], s0l);
            float u00 = __shfl_sync(0xffffffffu, sacc[kt8][0], s1l);
            float u01 = __shfl_sync(0xffffffffu, sacc[kt8][1], s1l);
            float u10 = __shfl_sync(0xffffffffu, sacc[kt8][2], s1l);
            float u11 = __shfl_sync(0xffffffffu, sacc[kt8][3], s1l);
            unsigned a[4];
            a[0] = f2tf((qm & 1) ? v01 : v00);   // (row,      key=qm)
            a[1] = f2tf((qm & 1) ? v11 : v10);   // (row+8,    key=qm)
            a[2] = f2tf((qm & 1) ? u01 : u00);   // (row,      key=qm+4)
            a[3] = f2tf((qm & 1) ? u11 : u10);   // (row+8,    key=qm+4)
            int kb = kt8 * 8 + qm;
            #pragma unroll
            for (int et = 0; et < 8; et++) {
                int e = et * 8 + gid;
                unsigned b[2] = { Vs[kb * 68 + e], Vs[(kb + 4) * 68 + e] };
                mma8(accO[et], a, b);
            }
        }
    }

    float inv0 = 1.f / lst[0], inv1 = 1.f / lst[1];
    int r = q0 + w * 16 + gid;
    #pragma unroll
    for (int et = 0; et < 8; et++) {
        int c = hc + et * 8 + 2 * qm;
        Oc[r * DM + c]           = accO[et][0] * inv0;
        Oc[r * DM + c + 1]       = accO[et][1] * inv0;
        Oc[(r + 8) * DM + c]     = accO[et][2] * inv1;
        Oc[(r + 8) * DM + c + 1] = accO[et][3] * inv1;
    }
}

// ---------------------------------------------------------------------------
extern "C" void kernel_launch(void* const* d_in, const int* in_sizes, int n_in,
                              void* d_out, int out_size) {
    const float* q  = (const float*)d_in[0];
    const float* k  = (const float*)d_in[1];
    const float* v  = (const float*)d_in[2];
    const float* Wq = (const float*)d_in[3];
    const float* bq = (const float*)d_in[4];
    const float* Wk = (const float*)d_in[5];
    const float* bk = (const float*)d_in[6];
    const float* Wv = (const float*)d_in[7];
    const float* bv = (const float*)d_in[8];
    const float* Wo = (const float*)d_in[9];
    const float* bo = (const float*)d_in[10];
    float* out = (float*)d_out;

    void *pQ, *pK, *pV, *pO;
    cudaGetSymbolAddress(&pQ, g_Qc);
    cudaGetSymbolAddress(&pK, g_Kc);
    cudaGetSymbolAddress(&pV, g_Vc);
    cudaGetSymbolAddress(&pO, g_Oc);
    float* Qc = (float*)pQ;
    float* Kc = (float*)pK;
    float* Vc = (float*)pV;
    float* Oc = (float*)pO;

    const int flash_smem = (128 * 68 + 2 * 64 * 68) * (int)sizeof(unsigned);  // 69632
    cudaFuncSetAttribute(flash_tf32, cudaFuncAttributeMaxDynamicSharedMemorySize,
                         flash_smem);

    dim3 blk(256);
    dim3 gg(SQ / 128, DM / 128);      // 32 x 8
    gemm_tf32<<<gg, blk>>>(q, Wq, bq, Qc, 1);
    gemm_tf32<<<gg, blk>>>(k, Wk, bk, Kc, 1);
    gemm_tf32<<<gg, blk>>>(v, Wv, bv, Vc, 1);

    dim3 gf(SQ / 128, NH);            // 32 x 16
    flash_tf32<<<gf, blk, flash_smem>>>(Qc, Kc, Vc, Oc);

    gemm_tf32<<<gg, blk>>>(Oc, Wo, bo, out, 0);
}